// round 3
// baseline (speedup 1.0000x reference)
#include <cuda_runtime.h>

// Problem constants
#define B_   64
#define C_   256
#define HW_  4096
#define EMB_ 512
#define BT   8      // batches per warp in stage kernels

// Scratch (allocation-free rule: __device__ globals)
__device__ float g_t1[B_ * C_];   // v_in
__device__ float g_t2[B_ * C_];   // v
__device__ float g_av[B_ * C_];   // final additive vector

// ---------------------------------------------------------------------------
// Stage: out[b*C + r] = dot(W[r], in[b], LEN) + bias[r], batch-tiled.
// One warp handles row r for BT consecutive batches: the weight row is read
// once per BT batches (8x less L2 weight traffic), inputs are L1-resident.
// Grid: C_ * (B_/BT) / 8 = 256 blocks x 256 threads.
// ---------------------------------------------------------------------------
template <int LEN>
__global__ void __launch_bounds__(256) stage_kernel(
    const float* __restrict__ W,      // (C_, LEN) row-major (pre-offset by caller)
    const float* __restrict__ invec,  // (B_, LEN)
    const float* __restrict__ bias,   // (C_,) pre-offset
    float* __restrict__ out)          // (B_, C_)
{
    const int warp = threadIdx.x >> 5;
    const int lane = threadIdx.x & 31;
    const int w    = blockIdx.x * 8 + warp;   // 0 .. C_*(B_/BT)-1 = 2047
    const int r    = w & (C_ - 1);            // row
    const int bg   = w >> 8;                  // batch group 0..7
    const int b0   = bg * BT;

    const float4* __restrict__ wrow = reinterpret_cast<const float4*>(W + (size_t)r * LEN);
    const float4* __restrict__ xin  = reinterpret_cast<const float4*>(invec + (size_t)b0 * LEN);

    float acc[BT];
    #pragma unroll
    for (int j = 0; j < BT; j++) acc[j] = 0.f;

    #pragma unroll
    for (int k = lane; k < LEN / 4; k += 32) {
        const float4 a = wrow[k];
        #pragma unroll
        for (int j = 0; j < BT; j++) {
            const float4 c = xin[(size_t)j * (LEN / 4) + k];
            acc[j] += a.x * c.x + a.y * c.y + a.z * c.z + a.w * c.w;
        }
    }

    #pragma unroll
    for (int j = 0; j < BT; j++) {
        #pragma unroll
        for (int o = 16; o > 0; o >>= 1)
            acc[j] += __shfl_down_sync(0xffffffffu, acc[j], o);
    }
    if (lane == 0) {
        const float bs = bias[r];
        #pragma unroll
        for (int j = 0; j < BT; j++)
            out[(size_t)(b0 + j) * C_ + r] = acc[j] + bs;
    }
}

// ---------------------------------------------------------------------------
// Kernel B: y[b,c,h,w] = x[b,c,h,w] + av[b,c]
// One block per (b,c) = 4096 contiguous floats = 1024 float4s.
// Plain loads/stores (streaming hints measured SLOWER on sm_103a).
// ---------------------------------------------------------------------------
__global__ void __launch_bounds__(256) broadcast_add_kernel(
    const float* __restrict__ x,
    float* __restrict__ y)
{
    const int bc = blockIdx.x;                 // 0 .. B*C-1
    const float a = g_av[bc];

    const float4* __restrict__ xi = reinterpret_cast<const float4*>(x) + (size_t)bc * (HW_ / 4);
    float4* __restrict__       yo = reinterpret_cast<float4*>(y)       + (size_t)bc * (HW_ / 4);

    #pragma unroll
    for (int t = 0; t < 4; t++) {
        const int i = threadIdx.x + t * 256;
        float4 v = xi[i];
        v.x += a; v.y += a; v.z += a; v.w += a;
        yo[i] = v;
    }
}

extern "C" void kernel_launch(void* const* d_in, const int* in_sizes, int n_in,
                              void* d_out, int out_size)
{
    // metadata order: x, cond_emb, ln_gamma, ln_beta, in_proj_w, in_proj_b,
    //                 out_w, out_b, kv_w, kv_b
    const float* x         = (const float*)d_in[0];
    const float* cond_emb  = (const float*)d_in[1];
    // ln_gamma/ln_beta provably do not affect the output: softmax over the
    // size-1 KV axis is exactly 1, so q (and thus x_ln) cancels.
    const float* in_proj_w = (const float*)d_in[4];
    const float* in_proj_b = (const float*)d_in[5];
    const float* out_w     = (const float*)d_in[6];
    const float* out_b     = (const float*)d_in[7];
    const float* kv_w      = (const float*)d_in[8];
    const float* kv_b      = (const float*)d_in[9];
    float* y = (float*)d_out;

    float *t1, *t2, *av;
    cudaGetSymbolAddress((void**)&t1, g_t1);
    cudaGetSymbolAddress((void**)&t2, g_t2);
    cudaGetSymbolAddress((void**)&av, g_av);

    const int grid = C_ * (B_ / BT) / 8;   // 256 blocks, one warp per (row, batch-group)

    // Stage 1: t1[b] = kv_w[C:2C] @ ce[b] + kv_b[C:]
    stage_kernel<EMB_><<<grid, 256>>>(kv_w + (size_t)C_ * EMB_, cond_emb,
                                      kv_b + C_, t1);
    // Stage 2: t2[b] = wv @ t1[b] + bv      (wv = in_proj_w rows [2C,3C))
    stage_kernel<C_><<<grid, 256>>>(in_proj_w + (size_t)2 * C_ * C_, t1,
                                    in_proj_b + 2 * C_, t2);
    // Stage 3: av[b] = out_w @ t2[b] + out_b
    stage_kernel<C_><<<grid, 256>>>(out_w, t2, out_b, av);

    // y = x + av broadcast
    broadcast_add_kernel<<<B_ * C_, 256>>>(x, y);
}